// round 10
// baseline (speedup 1.0000x reference)
#include <cuda_runtime.h>
#include <cuda_bf16.h>
#include <math.h>

#define N3   16777216u           // 256^3
#define SSTR 257                 // smem row stride (float2)
#define BROW 392                 // per-copy bin stride (floats), 3*129=387 used
#define NCPY 4

typedef unsigned long long u64c;   // packed complex: lo=re, hi=im (f32x2 lanes)

__device__ __nv_bfloat162 g_work[2u * N3];  // packed ref+i*pred spectrum (bf16), 134MB
__device__ double g_bins[800];              // [vol][label*3+comp]

// ---------------------------------------------------------------------------
// Packed f32x2 complex helpers
// ---------------------------------------------------------------------------
__device__ __forceinline__ u64c pk2(float x, float y) {
    u64c r; asm("mov.b64 %0, {%1, %2};" : "=l"(r) : "f"(x), "f"(y)); return r;
}
__device__ __forceinline__ float2 upk2(u64c v) {
    float2 r; asm("mov.b64 {%0, %1}, %2;" : "=f"(r.x), "=f"(r.y) : "l"(v)); return r;
}
__device__ __forceinline__ u64c padd(u64c a, u64c b) {
    u64c r; asm("add.rn.f32x2 %0, %1, %2;" : "=l"(r) : "l"(a), "l"(b)); return r;
}
__device__ __forceinline__ u64c pmul(u64c a, u64c b) {
    u64c r; asm("mul.rn.f32x2 %0, %1, %2;" : "=l"(r) : "l"(a), "l"(b)); return r;
}
__device__ __forceinline__ u64c pfma(u64c a, u64c b, u64c c) {
    u64c r; asm("fma.rn.f32x2 %0, %1, %2, %3;" : "=l"(r) : "l"(a), "l"(b), "l"(c)); return r;
}
// (-im, re): multiply by +i
__device__ __forceinline__ u64c pbswap(u64c a) {
    u64c r;
    asm("{\n\t.reg .b32 l, h, nh;\n\t"
        "mov.b64 {l, h}, %1;\n\t"
        "xor.b32 nh, h, 0x80000000;\n\t"
        "mov.b64 %0, {nh, l};\n\t}" : "=l"(r) : "l"(a));
    return r;
}
// (im, -re): multiply by -i
__device__ __forceinline__ u64c pmulni(u64c a) {
    u64c r;
    asm("{\n\t.reg .b32 l, h, nl;\n\t"
        "mov.b64 {l, h}, %1;\n\t"
        "xor.b32 nl, l, 0x80000000;\n\t"
        "mov.b64 %0, {h, nl};\n\t}" : "=l"(r) : "l"(a));
    return r;
}

__device__ constexpr float TWCc[8] = { 1.0f,  0.9238795325112867f,  0.7071067811865476f,
                                       0.3826834323650898f, 0.0f, -0.3826834323650898f,
                                      -0.7071067811865476f, -0.9238795325112867f };
__device__ constexpr float TWSc[8] = { 0.0f, -0.3826834323650898f, -0.7071067811865476f,
                                      -0.9238795325112867f, -1.0f, -0.9238795325112867f,
                                      -0.7071067811865476f, -0.3826834323650898f };

__device__ __forceinline__ void pbfly(u64c& a, u64c& b, int widx) {
    u64c t;
    if (widx == 0)      t = b;
    else if (widx == 4) t = pmulni(b);
    else {
        const u64c WR = pk2(TWCc[widx], TWCc[widx]);
        const u64c WI = pk2(TWSc[widx], TWSc[widx]);
        t = pfma(pbswap(b), WI, pmul(b, WR));
    }
    const u64c NEG1 = pk2(-1.0f, -1.0f);
    u64c na = padd(a, t);
    b = pfma(t, NEG1, a);
    a = na;
}

__device__ __forceinline__ void pswap(u64c& a, u64c& b) { u64c t = a; a = b; b = t; }

__device__ __forceinline__ void fft16p(u64c v[16]) {
    pswap(v[1], v[8]);  pswap(v[2], v[4]);  pswap(v[3], v[12]);
    pswap(v[5], v[10]); pswap(v[7], v[14]); pswap(v[11], v[13]);
#pragma unroll
    for (int s = 1; s <= 4; s++) {
        const int m = 1 << s, hm = m >> 1;
#pragma unroll
        for (int k = 0; k < 16; k += m) {
#pragma unroll
            for (int j = 0; j < hm; j++)
                pbfly(v[k + j], v[k + j + hm], j << (4 - s));
        }
    }
}

// Twiddle by W_256^{t*k1}: scalar recurrence, packed storage.
__device__ __forceinline__ void twmulp(u64c v[16], int t) {
    float bs, bc;
    sincospif(-(float)t / 128.0f, &bs, &bc);
    float wr = bc, wi = bs;
#pragma unroll
    for (int k1 = 1; k1 < 16; k1++) {
        float2 x = upk2(v[k1]);
        float xr = x.x * wr - x.y * wi;
        float xi = x.x * wi + x.y * wr;
        v[k1] = pk2(xr, xi);
        float nr = wr * bc - wi * bs;
        float ni = wr * bs + wi * bc;
        wr = nr; wi = ni;
    }
}

// cp.async helpers (LDGSTS, 4-byte)
__device__ __forceinline__ void cpa4(void* smem_dst, const void* gmem_src) {
    unsigned saddr = (unsigned)__cvta_generic_to_shared(smem_dst);
    asm volatile("cp.async.ca.shared.global [%0], [%1], 4;\n"
                 :: "r"(saddr), "l"(gmem_src));
}
__device__ __forceinline__ void cpa_commit() {
    asm volatile("cp.async.commit_group;\n" ::: "memory");
}
__device__ __forceinline__ void cpa_wait0() {
    asm volatile("cp.async.wait_group 0;\n" ::: "memory");
}

// ---------------------------------------------------------------------------
__global__ void __launch_bounds__(256, 3)
k_pass0(const float* __restrict__ ref, const float* __restrict__ pred) {
    __shared__ float2 sh[16 * SSTR];
    const int tid = threadIdx.x;
    const int bid = blockIdx.x;
    const unsigned vol  = (unsigned)bid >> 12;
    const unsigned tile = (unsigned)bid & 4095u;
    const int l = tid >> 4;
    const int t = tid & 15;
    const unsigned base = vol * N3 + (tile * 16u + (unsigned)l) * 256u;

    u64c v[16];
#pragma unroll
    for (int n1 = 0; n1 < 16; n1++) {
        unsigned e = base + (unsigned)(n1 * 16 + t);
        v[n1] = pk2(ref[e], pred[e]);
    }
    fft16p(v);
    twmulp(v, t);
    float2* lb = &sh[l * SSTR];
#pragma unroll
    for (int k1 = 0; k1 < 16; k1++)
        *reinterpret_cast<u64c*>(&lb[t * 16 + k1]) = v[k1];
    __syncthreads();
#pragma unroll
    for (int n2 = 0; n2 < 16; n2++)
        v[n2] = *reinterpret_cast<const u64c*>(&lb[n2 * 16 + t]);
    fft16p(v);
#pragma unroll
    for (int k2 = 0; k2 < 16; k2++) {
        float2 f = upk2(v[k2]);
        g_work[base + (unsigned)(k2 * 16 + t)] = __float22bfloat162_rn(f);
    }
}

// ---------------------------------------------------------------------------
template<unsigned ES, unsigned OS>
__global__ void __launch_bounds__(256, 3) k_passS() {
    __shared__ float2 sh[16 * SSTR];
    const int tid = threadIdx.x;
    const int bid = blockIdx.x;
    const unsigned vol   = (unsigned)bid >> 12;
    const unsigned r     = (unsigned)bid & 4095u;
    const unsigned outer = r >> 4;
    const unsigned w0    = (r & 15u) * 16u;
    const int wl = tid & 15;
    const int t  = tid >> 4;
    const unsigned base = vol * N3 + outer * OS + w0 + (unsigned)wl;

    u64c v[16];
#pragma unroll
    for (int n1 = 0; n1 < 16; n1++) {
        float2 c = __bfloat1622float2(g_work[base + (unsigned)(n1 * 16 + t) * ES]);
        v[n1] = pk2(c.x, c.y);
    }
    fft16p(v);
    twmulp(v, t);
    float2* lb = &sh[wl * SSTR];
#pragma unroll
    for (int k1 = 0; k1 < 16; k1++)
        *reinterpret_cast<u64c*>(&lb[t * 16 + k1]) = v[k1];
    __syncthreads();
#pragma unroll
    for (int n2 = 0; n2 < 16; n2++)
        v[n2] = *reinterpret_cast<const u64c*>(&lb[n2 * 16 + t]);
    fft16p(v);
#pragma unroll
    for (int k2 = 0; k2 < 16; k2++) {
        float2 f = upk2(v[k2]);
        g_work[base + (unsigned)(k2 * 16 + t) * ES] = __float22bfloat162_rn(f);
    }
}

// ---------------------------------------------------------------------------
// Fused D-pass + shell reduction (validated logic; packed FFT math).
// ---------------------------------------------------------------------------
extern __shared__ float2 dynsh[];

__device__ __forceinline__ int slbl(int c2) {
    return min((int)__fsqrt_rn((float)c2), 128);
}
__device__ __forceinline__ void flushBins(float* bins, int l,
                                          float s0, float s1, float s2) {
    atomicAdd(&bins[l * 3 + 0], s0);
    atomicAdd(&bins[l * 3 + 1], s1);
    atomicAdd(&bins[l * 3 + 2], s2);
}

__device__ __forceinline__ void selfLine(const float2* L, int c2, float* bins, int t) {
    const int d0 = t * 8;
    int lcur = -1; float s0 = 0.f, s1 = 0.f, s2 = 0.f;
#pragma unroll
    for (int i = 0; i < 8; i++) {
        const int d = d0 + i;
        float q0, q1, q2;
        const float2 b = L[d];
        if (d == 0) {
            q0 = b.x * b.x + b.y * b.y;
            q1 = b.x * b.x - b.y * b.y;
            q2 = 2.0f * b.x * b.y;
        } else {
            const float2 a = L[256 - d];
            q0 = a.x * a.x + a.y * a.y + b.x * b.x + b.y * b.y;
            q1 = 2.0f * (a.x * b.x - a.y * b.y);
            q2 = 2.0f * (a.x * b.y + a.y * b.x);
        }
        const int l = slbl(c2 + d * d);
        if (l != lcur) {
            if (lcur >= 0) flushBins(bins, lcur, s0, s1, s2);
            lcur = l; s0 = q0; s1 = q1; s2 = q2;
        } else { s0 += q0; s1 += q1; s2 += q2; }
    }
    if (t == 15) {   // d = 128 self element
        const float2 b = L[128];
        const int l = slbl(c2 + 16384);
        float q0 = b.x * b.x + b.y * b.y;
        float q1 = b.x * b.x - b.y * b.y;
        float q2 = 2.0f * b.x * b.y;
        if (l != lcur) {
            if (lcur >= 0) flushBins(bins, lcur, s0, s1, s2);
            lcur = l; s0 = q0; s1 = q1; s2 = q2;
        } else { s0 += q0; s1 += q1; s2 += q2; }
    }
    if (lcur >= 0) flushBins(bins, lcur, s0, s1, s2);
}

__global__ void __launch_bounds__(256, 3) k_fusedD() {
    float2* bufA = dynsh;                       // 16*SSTR
    float2* bufB = dynsh + 16 * SSTR;           // 16*SSTR
    float*  sbf  = (float*)(dynsh + 32 * SSTR); // NCPY*BROW floats

    const int tid = threadIdx.x;

    const unsigned bid = blockIdx.x;
    const unsigned vol = bid >> 11;
    const unsigned r   = bid & 2047u;
    const unsigned volBase = vol * N3;

    unsigned hA, c;
    bool special = false;
    if (r < 2032u) { hA = 1u + (r >> 4); c = r & 15u; }
    else {
        unsigned idx = r - 2032u;
        hA = (idx < 8u) ? 0u : 128u;
        c  = idx & 7u;
        special = (c == 0u);
    }
    const unsigned hB = (256u - hA) & 255u;

    const int wl = tid & 15;
    const int t  = tid >> 4;

    const unsigned wA = 16u * c + (unsigned)wl;
    unsigned wB = (256u - 16u * c - (unsigned)wl) & 255u;
    if (special && wl == 0) wB = 128u;   // avoid duplicating w=0 line

    const unsigned baseA = volBase + hA * 256u + wA;
    const unsigned baseB = volBase + hB * 256u + wB;

    u64c v[16];
    float2* la = &bufA[wl * SSTR];
    float2* rb = &bufB[wl * SSTR];

    // ---- B lines: async bf16x2 staging into LOW half of own float2 slots ----
#pragma unroll
    for (int n1 = 0; n1 < 16; n1++)
        cpa4(&rb[t * 16 + n1], &g_work[baseB + (unsigned)(n1 * 16 + t) * 65536u]);
    cpa_commit();

    // ---- A lines into registers (bf16 -> fp32, packed) ----
#pragma unroll
    for (int n1 = 0; n1 < 16; n1++) {
        float2 cA = __bfloat1622float2(g_work[baseA + (unsigned)(n1 * 16 + t) * 65536u]);
        v[n1] = pk2(cA.x, cA.y);
    }

    for (int i = tid; i < NCPY * BROW; i += 256) sbf[i] = 0.0f;

    // ---- phase A ----
    fft16p(v);
    twmulp(v, t);
#pragma unroll
    for (int k1 = 0; k1 < 16; k1++)
        *reinterpret_cast<u64c*>(&la[t * 16 + k1]) = v[k1];
    __syncthreads();                                    // (1)
#pragma unroll
    for (int n2 = 0; n2 < 16; n2++)
        v[n2] = *reinterpret_cast<const u64c*>(&la[n2 * 16 + t]);
    fft16p(v);
#pragma unroll
    for (int k2 = 0; k2 < 16; k2++)
        *reinterpret_cast<u64c*>(&la[k2 * 16 + t]) = v[k2];  // own slots

    // ---- phase B from staged bf16 (own slots; per-thread wait only) ----
    cpa_wait0();
#pragma unroll
    for (int n1 = 0; n1 < 16; n1++) {
        __nv_bfloat162 raw = *reinterpret_cast<const __nv_bfloat162*>(&rb[t * 16 + n1]);
        float2 cB = __bfloat1622float2(raw);
        v[n1] = pk2(cB.x, cB.y);
    }
    fft16p(v);
    twmulp(v, t);
#pragma unroll
    for (int k1 = 0; k1 < 16; k1++)
        *reinterpret_cast<u64c*>(&rb[t * 16 + k1]) = v[k1];  // overwrite own slots
    __syncthreads();                                    // (2)
#pragma unroll
    for (int n2 = 0; n2 < 16; n2++)
        v[n2] = *reinterpret_cast<const u64c*>(&rb[n2 * 16 + t]);
    fft16p(v);
#pragma unroll
    for (int k2 = 0; k2 < 16; k2++)
        *reinterpret_cast<u64c*>(&rb[k2 * 16 + t]) = v[k2];  // own slots
    __syncthreads();                                    // (3)

    // ---- binning: half-line windows, 4 elements per label sample ----
    float* bins = sbf + (wl & 3) * BROW;

    if (special && wl == 0) {
        const int shh = (hB < 128u) ? (int)hB : (int)hB - 256;
        selfLine(&bufA[0], shh * shh,          bins, t);   // (h, w=0)
        selfLine(&bufB[0], shh * shh + 16384,  bins, t);   // (h, w=128)
    } else {
        const int shh = (hB < 128u) ? (int)hB : (int)hB - 256;
        const int sww = (wB < 128u) ? (int)wB : (int)wB - 256;
        const int c2hw = shh * shh + sww * sww;
        const float2* A = la;
        const float2* B = rb;
        const int d0 = t * 8;
        int lcur = -1; float s0 = 0.f, s1 = 0.f, s2 = 0.f;
#pragma unroll
        for (int i = 0; i < 8; i++) {
            const int d = d0 + i;
            float q0, q1, q2;
            if (d == 0) {
                const float2 a = A[0], b = B[0];
                q0 = a.x * a.x + a.y * a.y + b.x * b.x + b.y * b.y;
                q1 = 2.0f * (a.x * b.x - a.y * b.y);
                q2 = 2.0f * (a.x * b.y + a.y * b.x);
            } else {
                const float2 b1 = B[d],       a1 = A[256 - d];
                const float2 b2 = B[256 - d], a2 = A[d];
                q0 = a1.x * a1.x + a1.y * a1.y + b1.x * b1.x + b1.y * b1.y
                   + a2.x * a2.x + a2.y * a2.y + b2.x * b2.x + b2.y * b2.y;
                q1 = 2.0f * (a1.x * b1.x - a1.y * b1.y + a2.x * b2.x - a2.y * b2.y);
                q2 = 2.0f * (a1.x * b1.y + a1.y * b1.x + a2.x * b2.y + a2.y * b2.x);
            }
            const int l = slbl(c2hw + d * d);
            if (l != lcur) {
                if (lcur >= 0) flushBins(bins, lcur, s0, s1, s2);
                lcur = l; s0 = q0; s1 = q1; s2 = q2;
            } else { s0 += q0; s1 += q1; s2 += q2; }
        }
        if (t == 15) {   // d = 128: single pair (A[128], B[128])
            const float2 a = A[128], b = B[128];
            const float q0 = a.x * a.x + a.y * a.y + b.x * b.x + b.y * b.y;
            const float q1 = 2.0f * (a.x * b.x - a.y * b.y);
            const float q2 = 2.0f * (a.x * b.y + a.y * b.x);
            const int l = slbl(c2hw + 16384);
            if (l != lcur) {
                if (lcur >= 0) flushBins(bins, lcur, s0, s1, s2);
                lcur = l; s0 = q0; s1 = q1; s2 = q2;
            } else { s0 += q0; s1 += q1; s2 += q2; }
        }
        if (lcur >= 0) flushBins(bins, lcur, s0, s1, s2);
    }
    __syncthreads();

    for (int i = tid; i < 387; i += 256) {
        float s = 0.0f;
#pragma unroll
        for (int cpy = 0; cpy < NCPY; cpy++) s += sbf[cpy * BROW + i];
        atomicAdd(&g_bins[vol * 400u + (unsigned)i], (double)s);
    }
}

// ---------------------------------------------------------------------------
__global__ void k_final(float* out) {
    __shared__ double red[256];
    const int tid = threadIdx.x;
    const unsigned vol = (unsigned)tid >> 7;
    const unsigned bin = (unsigned)tid & 127u;
    const double S0 = g_bins[vol * 400u + bin * 3u + 0u];
    const double S1 = g_bins[vol * 400u + bin * 3u + 1u];
    const double S2 = g_bins[vol * 400u + bin * 3u + 2u];
    const double num = 0.5 * S2;
    const double d1 = 0.5 * (S0 + S1);
    const double d2 = 0.5 * (S0 - S1);
    const double f2 = (num * num) / (d1 * d2 + 1e-8);
    red[tid] = f2;
    __syncthreads();
    for (int s = 128; s > 0; s >>= 1) {
        if (tid < s) red[tid] += red[tid + s];
        __syncthreads();
    }
    if (tid == 0) out[0] = (float)(1.0 - red[0] / 256.0);
}

__global__ void k_zero() {
    int i = blockIdx.x * blockDim.x + threadIdx.x;
    if (i < 800) g_bins[i] = 0.0;
}

// ---------------------------------------------------------------------------
extern "C" void kernel_launch(void* const* d_in, const int* in_sizes, int n_in,
                              void* d_out, int out_size) {
    const float* ref  = (const float*)d_in[0];
    const float* pred = (const float*)d_in[1];
    float* out = (float*)d_out;

    const int FUSED_SMEM = 32 * SSTR * 8 + NCPY * BROW * 4;  // 72064 B
    cudaFuncSetAttribute(k_fusedD, cudaFuncAttributeMaxDynamicSharedMemorySize,
                         FUSED_SMEM);

    k_zero<<<4, 256>>>();
    k_pass0<<<8192, 256>>>(ref, pred);                 // pack + FFT along W
    k_passS<256u, 65536u><<<8192, 256>>>();            // FFT along H
    k_fusedD<<<4096, 256, FUSED_SMEM>>>();             // FFT along D + binning
    k_final<<<1, 256>>>(out);                          // scalar loss
}

// round 11
// speedup vs baseline: 1.3950x; 1.3950x over previous
#include <cuda_runtime.h>
#include <cuda_bf16.h>
#include <math.h>

#define N3   16777216u           // 256^3
#define SSTR 257                 // smem row stride (float2)
#define BROW 392                 // per-copy bin stride (floats), 3*129=387 used
#define NCPY 4

__device__ __nv_bfloat162 g_work[2u * N3];  // packed ref+i*pred spectrum (bf16), 134MB
__device__ double g_bins[800];              // [vol][label*3+comp]

// ---------------------------------------------------------------------------
__constant__ float TW16C[8] = { 1.0f,  0.9238795325112867f,  0.7071067811865476f,
                                0.3826834323650898f, 0.0f, -0.3826834323650898f,
                               -0.7071067811865476f, -0.9238795325112867f };
__constant__ float TW16S[8] = { 0.0f, -0.3826834323650898f, -0.7071067811865476f,
                               -0.9238795325112867f, -1.0f, -0.9238795325112867f,
                               -0.7071067811865476f, -0.9238795325112867f };
// NOTE: last entry corrected below in a static_assert-safe way
__constant__ float TW16S_FIX[8] = { 0.0f, -0.3826834323650898f, -0.7071067811865476f,
                                   -0.9238795325112867f, -1.0f, -0.9238795325112867f,
                                   -0.7071067811865476f, -0.3826834323650898f };

__device__ __forceinline__ void cswap(float2& a, float2& b) { float2 t = a; a = b; b = t; }

__device__ __forceinline__ void fft16(float2 v[16]) {
    cswap(v[1], v[8]);  cswap(v[2], v[4]);  cswap(v[3], v[12]);
    cswap(v[5], v[10]); cswap(v[7], v[14]); cswap(v[11], v[13]);
#pragma unroll
    for (int s = 1; s <= 4; s++) {
        const int m = 1 << s, hm = m >> 1;
#pragma unroll
        for (int k = 0; k < 16; k += m) {
#pragma unroll
            for (int j = 0; j < hm; j++) {
                const float wr = TW16C[j << (4 - s)];
                const float wi = TW16S_FIX[j << (4 - s)];
                float2 a = v[k + j], b = v[k + j + hm];
                float tr = b.x * wr - b.y * wi;
                float ti = b.x * wi + b.y * wr;
                v[k + j]      = make_float2(a.x + tr, a.y + ti);
                v[k + j + hm] = make_float2(a.x - tr, a.y - ti);
            }
        }
    }
}

__device__ __forceinline__ void twmul(float2 v[16], int t) {
    float bs, bc;
    sincospif(-(float)t / 128.0f, &bs, &bc);
    float wr = bc, wi = bs;
#pragma unroll
    for (int k1 = 1; k1 < 16; k1++) {
        float xr = v[k1].x * wr - v[k1].y * wi;
        float xi = v[k1].x * wi + v[k1].y * wr;
        v[k1] = make_float2(xr, xi);
        float nr = wr * bc - wi * bs;
        float ni = wr * bs + wi * bc;
        wr = nr; wi = ni;
    }
}

// cp.async helpers (LDGSTS, 4-byte)
__device__ __forceinline__ void cpa4(void* smem_dst, const void* gmem_src) {
    unsigned saddr = (unsigned)__cvta_generic_to_shared(smem_dst);
    asm volatile("cp.async.ca.shared.global [%0], [%1], 4;\n"
                 :: "r"(saddr), "l"(gmem_src));
}
__device__ __forceinline__ void cpa_commit() {
    asm volatile("cp.async.commit_group;\n" ::: "memory");
}
__device__ __forceinline__ void cpa_wait0() {
    asm volatile("cp.async.wait_group 0;\n" ::: "memory");
}

// ---------------------------------------------------------------------------
__global__ void __launch_bounds__(256, 3)
k_pass0(const float* __restrict__ ref, const float* __restrict__ pred) {
    __shared__ float2 sh[16 * SSTR];
    const int tid = threadIdx.x;
    const int bid = blockIdx.x;

    // fold former k_zero: block 0 clears the bin accumulators (pass0 fully
    // precedes k_fusedD, which is the only reader/writer of g_bins after).
    if (bid == 0) {
        for (int i = tid; i < 800; i += 256) g_bins[i] = 0.0;
    }

    const unsigned vol  = (unsigned)bid >> 12;
    const unsigned tile = (unsigned)bid & 4095u;
    const int l = tid >> 4;
    const int t = tid & 15;
    const unsigned base = vol * N3 + (tile * 16u + (unsigned)l) * 256u;

    float2 v[16];
#pragma unroll
    for (int n1 = 0; n1 < 16; n1++) {
        unsigned e = base + (unsigned)(n1 * 16 + t);
        v[n1] = make_float2(ref[e], pred[e]);
    }
    fft16(v);
    twmul(v, t);
    float2* lb = &sh[l * SSTR];
#pragma unroll
    for (int k1 = 0; k1 < 16; k1++) lb[t * 16 + k1] = v[k1];
    __syncthreads();
#pragma unroll
    for (int n2 = 0; n2 < 16; n2++) v[n2] = lb[n2 * 16 + t];
    fft16(v);
#pragma unroll
    for (int k2 = 0; k2 < 16; k2++)
        g_work[base + (unsigned)(k2 * 16 + t)] = __float22bfloat162_rn(v[k2]);
}

// ---------------------------------------------------------------------------
template<unsigned ES, unsigned OS>
__global__ void __launch_bounds__(256, 3) k_passS() {
    __shared__ float2 sh[16 * SSTR];
    const int tid = threadIdx.x;
    const int bid = blockIdx.x;
    const unsigned vol   = (unsigned)bid >> 12;
    const unsigned r     = (unsigned)bid & 4095u;
    const unsigned outer = r >> 4;
    const unsigned w0    = (r & 15u) * 16u;
    const int wl = tid & 15;
    const int t  = tid >> 4;
    const unsigned base = vol * N3 + outer * OS + w0 + (unsigned)wl;

    float2 v[16];
#pragma unroll
    for (int n1 = 0; n1 < 16; n1++)
        v[n1] = __bfloat1622float2(g_work[base + (unsigned)(n1 * 16 + t) * ES]);
    fft16(v);
    twmul(v, t);
    float2* lb = &sh[wl * SSTR];
#pragma unroll
    for (int k1 = 0; k1 < 16; k1++) lb[t * 16 + k1] = v[k1];
    __syncthreads();
#pragma unroll
    for (int n2 = 0; n2 < 16; n2++) v[n2] = lb[n2 * 16 + t];
    fft16(v);
#pragma unroll
    for (int k2 = 0; k2 < 16; k2++)
        g_work[base + (unsigned)(k2 * 16 + t) * ES] = __float22bfloat162_rn(v[k2]);
}

// ---------------------------------------------------------------------------
// Fused D-pass + shell reduction. B lines staged via cp.async (bf16x2, lands
// in the low half of the thread's OWN float2 slot -> no extra barrier).
// ---------------------------------------------------------------------------
extern __shared__ float2 dynsh[];

__device__ __forceinline__ int slbl(int c2) {
    return min((int)__fsqrt_rn((float)c2), 128);
}
__device__ __forceinline__ void flushBins(float* bins, int l,
                                          float s0, float s1, float s2) {
    atomicAdd(&bins[l * 3 + 0], s0);
    atomicAdd(&bins[l * 3 + 1], s1);
    atomicAdd(&bins[l * 3 + 2], s2);
}

// Self-mirror line binning: L holds Z of a line with w,h both self-mirror.
__device__ __forceinline__ void selfLine(const float2* L, int c2, float* bins, int t) {
    const int d0 = t * 8;
    int lcur = -1; float s0 = 0.f, s1 = 0.f, s2 = 0.f;
#pragma unroll
    for (int i = 0; i < 8; i++) {
        const int d = d0 + i;
        float q0, q1, q2;
        const float2 b = L[d];
        if (d == 0) {
            q0 = b.x * b.x + b.y * b.y;
            q1 = b.x * b.x - b.y * b.y;
            q2 = 2.0f * b.x * b.y;
        } else {
            const float2 a = L[256 - d];
            q0 = a.x * a.x + a.y * a.y + b.x * b.x + b.y * b.y;
            q1 = 2.0f * (a.x * b.x - a.y * b.y);
            q2 = 2.0f * (a.x * b.y + a.y * b.x);
        }
        const int l = slbl(c2 + d * d);
        if (l != lcur) {
            if (lcur >= 0) flushBins(bins, lcur, s0, s1, s2);
            lcur = l; s0 = q0; s1 = q1; s2 = q2;
        } else { s0 += q0; s1 += q1; s2 += q2; }
    }
    if (t == 15) {   // d = 128 self element
        const float2 b = L[128];
        const int l = slbl(c2 + 16384);
        float q0 = b.x * b.x + b.y * b.y;
        float q1 = b.x * b.x - b.y * b.y;
        float q2 = 2.0f * b.x * b.y;
        if (l != lcur) {
            if (lcur >= 0) flushBins(bins, lcur, s0, s1, s2);
            lcur = l; s0 = q0; s1 = q1; s2 = q2;
        } else { s0 += q0; s1 += q1; s2 += q2; }
    }
    if (lcur >= 0) flushBins(bins, lcur, s0, s1, s2);
}

__global__ void __launch_bounds__(256, 3) k_fusedD() {
    float2* bufA = dynsh;                       // 16*SSTR
    float2* bufB = dynsh + 16 * SSTR;           // 16*SSTR
    float*  sbf  = (float*)(dynsh + 32 * SSTR); // NCPY*BROW floats

    const int tid = threadIdx.x;

    const unsigned bid = blockIdx.x;
    const unsigned vol = bid >> 11;
    const unsigned r   = bid & 2047u;
    const unsigned volBase = vol * N3;

    unsigned hA, c;
    bool special = false;
    if (r < 2032u) { hA = 1u + (r >> 4); c = r & 15u; }
    else {
        unsigned idx = r - 2032u;
        hA = (idx < 8u) ? 0u : 128u;
        c  = idx & 7u;
        special = (c == 0u);
    }
    const unsigned hB = (256u - hA) & 255u;

    const int wl = tid & 15;
    const int t  = tid >> 4;

    const unsigned wA = 16u * c + (unsigned)wl;
    unsigned wB = (256u - 16u * c - (unsigned)wl) & 255u;
    if (special && wl == 0) wB = 128u;   // avoid duplicating w=0 line

    const unsigned baseA = volBase + hA * 256u + wA;
    const unsigned baseB = volBase + hB * 256u + wB;

    float2 v[16];
    float2* la = &bufA[wl * SSTR];
    float2* rb = &bufB[wl * SSTR];

    // ---- B lines: async bf16x2 staging into LOW half of own float2 slots ----
#pragma unroll
    for (int n1 = 0; n1 < 16; n1++)
        cpa4(&rb[t * 16 + n1], &g_work[baseB + (unsigned)(n1 * 16 + t) * 65536u]);
    cpa_commit();

    // ---- A lines into registers (bf16 -> fp32) ----
#pragma unroll
    for (int n1 = 0; n1 < 16; n1++)
        v[n1] = __bfloat1622float2(g_work[baseA + (unsigned)(n1 * 16 + t) * 65536u]);

    for (int i = tid; i < NCPY * BROW; i += 256) sbf[i] = 0.0f;

    // ---- phase A ----
    fft16(v);
    twmul(v, t);
#pragma unroll
    for (int k1 = 0; k1 < 16; k1++) la[t * 16 + k1] = v[k1];
    __syncthreads();                                    // (1)
#pragma unroll
    for (int n2 = 0; n2 < 16; n2++) v[n2] = la[n2 * 16 + t];
    fft16(v);
#pragma unroll
    for (int k2 = 0; k2 < 16; k2++) la[k2 * 16 + t] = v[k2];  // own slots

    // ---- phase B from staged bf16 (own slots; per-thread wait only) ----
    cpa_wait0();
#pragma unroll
    for (int n1 = 0; n1 < 16; n1++) {
        __nv_bfloat162 raw = *reinterpret_cast<const __nv_bfloat162*>(&rb[t * 16 + n1]);
        v[n1] = __bfloat1622float2(raw);
    }
    fft16(v);
    twmul(v, t);
#pragma unroll
    for (int k1 = 0; k1 < 16; k1++) rb[t * 16 + k1] = v[k1];  // overwrite own slots
    __syncthreads();                                    // (2)
#pragma unroll
    for (int n2 = 0; n2 < 16; n2++) v[n2] = rb[n2 * 16 + t];
    fft16(v);
#pragma unroll
    for (int k2 = 0; k2 < 16; k2++) rb[k2 * 16 + t] = v[k2];  // own slots
    __syncthreads();                                    // (3)

    // ---- binning: half-line windows, 4 elements per label sample ----
    float* bins = sbf + (wl & 3) * BROW;

    if (special && wl == 0) {
        const int shh = (hB < 128u) ? (int)hB : (int)hB - 256;
        selfLine(&bufA[0], shh * shh,          bins, t);   // (h, w=0)
        selfLine(&bufB[0], shh * shh + 16384,  bins, t);   // (h, w=128)
    } else {
        const int shh = (hB < 128u) ? (int)hB : (int)hB - 256;
        const int sww = (wB < 128u) ? (int)wB : (int)wB - 256;
        const int c2hw = shh * shh + sww * sww;
        const float2* A = la;
        const float2* B = rb;
        const int d0 = t * 8;
        int lcur = -1; float s0 = 0.f, s1 = 0.f, s2 = 0.f;
#pragma unroll
        for (int i = 0; i < 8; i++) {
            const int d = d0 + i;
            float q0, q1, q2;
            if (d == 0) {
                const float2 a = A[0], b = B[0];
                q0 = a.x * a.x + a.y * a.y + b.x * b.x + b.y * b.y;
                q1 = 2.0f * (a.x * b.x - a.y * b.y);
                q2 = 2.0f * (a.x * b.y + a.y * b.x);
            } else {
                const float2 b1 = B[d],       a1 = A[256 - d];
                const float2 b2 = B[256 - d], a2 = A[d];
                q0 = a1.x * a1.x + a1.y * a1.y + b1.x * b1.x + b1.y * b1.y
                   + a2.x * a2.x + a2.y * a2.y + b2.x * b2.x + b2.y * b2.y;
                q1 = 2.0f * (a1.x * b1.x - a1.y * b1.y + a2.x * b2.x - a2.y * b2.y);
                q2 = 2.0f * (a1.x * b1.y + a1.y * b1.x + a2.x * b2.y + a2.y * b2.x);
            }
            const int l = slbl(c2hw + d * d);
            if (l != lcur) {
                if (lcur >= 0) flushBins(bins, lcur, s0, s1, s2);
                lcur = l; s0 = q0; s1 = q1; s2 = q2;
            } else { s0 += q0; s1 += q1; s2 += q2; }
        }
        if (t == 15) {   // d = 128: single pair (A[128], B[128])
            const float2 a = A[128], b = B[128];
            const float q0 = a.x * a.x + a.y * a.y + b.x * b.x + b.y * b.y;
            const float q1 = 2.0f * (a.x * b.x - a.y * b.y);
            const float q2 = 2.0f * (a.x * b.y + a.y * b.x);
            const int l = slbl(c2hw + 16384);
            if (l != lcur) {
                if (lcur >= 0) flushBins(bins, lcur, s0, s1, s2);
                lcur = l; s0 = q0; s1 = q1; s2 = q2;
            } else { s0 += q0; s1 += q1; s2 += q2; }
        }
        if (lcur >= 0) flushBins(bins, lcur, s0, s1, s2);
    }
    __syncthreads();

    for (int i = tid; i < 387; i += 256) {
        float s = 0.0f;
#pragma unroll
        for (int cpy = 0; cpy < NCPY; cpy++) s += sbf[cpy * BROW + i];
        atomicAdd(&g_bins[vol * 400u + (unsigned)i], (double)s);
    }
}

// ---------------------------------------------------------------------------
__global__ void k_final(float* out) {
    __shared__ double red[256];
    const int tid = threadIdx.x;
    const unsigned vol = (unsigned)tid >> 7;
    const unsigned bin = (unsigned)tid & 127u;
    const double S0 = g_bins[vol * 400u + bin * 3u + 0u];
    const double S1 = g_bins[vol * 400u + bin * 3u + 1u];
    const double S2 = g_bins[vol * 400u + bin * 3u + 2u];
    const double num = 0.5 * S2;
    const double d1 = 0.5 * (S0 + S1);
    const double d2 = 0.5 * (S0 - S1);
    const double f2 = (num * num) / (d1 * d2 + 1e-8);
    red[tid] = f2;
    __syncthreads();
    for (int s = 128; s > 0; s >>= 1) {
        if (tid < s) red[tid] += red[tid + s];
        __syncthreads();
    }
    if (tid == 0) out[0] = (float)(1.0 - red[0] / 256.0);
}

// ---------------------------------------------------------------------------
extern "C" void kernel_launch(void* const* d_in, const int* in_sizes, int n_in,
                              void* d_out, int out_size) {
    const float* ref  = (const float*)d_in[0];
    const float* pred = (const float*)d_in[1];
    float* out = (float*)d_out;

    const int FUSED_SMEM = 32 * SSTR * 8 + NCPY * BROW * 4;  // 72064 B
    cudaFuncSetAttribute(k_fusedD, cudaFuncAttributeMaxDynamicSharedMemorySize,
                         FUSED_SMEM);

    k_pass0<<<8192, 256>>>(ref, pred);                 // zero bins + pack + FFT along W
    k_passS<256u, 65536u><<<8192, 256>>>();            // FFT along H
    k_fusedD<<<4096, 256, FUSED_SMEM>>>();             // FFT along D + binning
    k_final<<<1, 256>>>(out);                          // scalar loss
}

// round 13
// speedup vs baseline: 1.4036x; 1.0062x over previous
#include <cuda_runtime.h>
#include <cuda_bf16.h>
#include <math.h>

#define N3   16777216u           // 256^3
#define SSTR 257                 // smem row stride (float2)
#define BROW 392                 // per-copy bin stride (floats), 3*129=387 used
#define NCPY 4

__device__ __nv_bfloat162 g_work[2u * N3];  // packed ref+i*pred spectrum (bf16), 134MB
__device__ double g_bins[800];              // [vol][label*3+comp]
__device__ int    g_ctr = 0;                // last-block counter (self-resetting)

// ---------------------------------------------------------------------------
// constexpr twiddles: folded to FFMA immediates by nvcc (no LDC on sm_103a).
// ---------------------------------------------------------------------------
__device__ constexpr float TWC[8] = { 1.0f,  0.9238795325112867f,  0.7071067811865476f,
                                      0.3826834323650898f, 0.0f, -0.3826834323650898f,
                                     -0.7071067811865476f, -0.9238795325112867f };
__device__ constexpr float TWS[8] = { 0.0f, -0.3826834323650898f, -0.7071067811865476f,
                                     -0.9238795325112867f, -1.0f, -0.9238795325112867f,
                                     -0.7071067811865476f, -0.3826834323650898f };

__device__ __forceinline__ void cswap(float2& a, float2& b) { float2 t = a; a = b; b = t; }

__device__ __forceinline__ void fft16(float2 v[16]) {
    cswap(v[1], v[8]);  cswap(v[2], v[4]);  cswap(v[3], v[12]);
    cswap(v[5], v[10]); cswap(v[7], v[14]); cswap(v[11], v[13]);
#pragma unroll
    for (int s = 1; s <= 4; s++) {
        const int m = 1 << s, hm = m >> 1;
#pragma unroll
        for (int k = 0; k < 16; k += m) {
#pragma unroll
            for (int j = 0; j < hm; j++) {
                const float wr = TWC[j << (4 - s)];   // literal -> folded
                const float wi = TWS[j << (4 - s)];   // literal -> folded
                float2 a = v[k + j], b = v[k + j + hm];
                float tr = b.x * wr - b.y * wi;
                float ti = b.x * wi + b.y * wr;
                v[k + j]      = make_float2(a.x + tr, a.y + ti);
                v[k + j + hm] = make_float2(a.x - tr, a.y - ti);
            }
        }
    }
}

__device__ __forceinline__ void twmul(float2 v[16], int t) {
    float bs, bc;
    sincospif(-(float)t / 128.0f, &bs, &bc);
    float wr = bc, wi = bs;
#pragma unroll
    for (int k1 = 1; k1 < 16; k1++) {
        float xr = v[k1].x * wr - v[k1].y * wi;
        float xi = v[k1].x * wi + v[k1].y * wr;
        v[k1] = make_float2(xr, xi);
        float nr = wr * bc - wi * bs;
        float ni = wr * bs + wi * bc;
        wr = nr; wi = ni;
    }
}

// cp.async helpers (LDGSTS, 4-byte)
__device__ __forceinline__ void cpa4(void* smem_dst, const void* gmem_src) {
    unsigned saddr = (unsigned)__cvta_generic_to_shared(smem_dst);
    asm volatile("cp.async.ca.shared.global [%0], [%1], 4;\n"
                 :: "r"(saddr), "l"(gmem_src));
}
__device__ __forceinline__ void cpa_commit() {
    asm volatile("cp.async.commit_group;\n" ::: "memory");
}
__device__ __forceinline__ void cpa_wait0() {
    asm volatile("cp.async.wait_group 0;\n" ::: "memory");
}

// ---------------------------------------------------------------------------
__global__ void __launch_bounds__(256, 3)
k_pass0(const float* __restrict__ ref, const float* __restrict__ pred) {
    __shared__ float2 sh[16 * SSTR];
    const int tid = threadIdx.x;
    const int bid = blockIdx.x;

    // block 0 clears the bin accumulators (pass0 precedes fusedD).
    if (bid == 0) {
        for (int i = tid; i < 800; i += 256) g_bins[i] = 0.0;
    }

    const unsigned vol  = (unsigned)bid >> 12;
    const unsigned tile = (unsigned)bid & 4095u;
    const int l = tid >> 4;
    const int t = tid & 15;
    const unsigned base = vol * N3 + (tile * 16u + (unsigned)l) * 256u;

    float2 v[16];
#pragma unroll
    for (int n1 = 0; n1 < 16; n1++) {
        unsigned e = base + (unsigned)(n1 * 16 + t);
        v[n1] = make_float2(ref[e], pred[e]);
    }
    fft16(v);
    twmul(v, t);
    float2* lb = &sh[l * SSTR];
#pragma unroll
    for (int k1 = 0; k1 < 16; k1++) lb[t * 16 + k1] = v[k1];
    __syncthreads();
#pragma unroll
    for (int n2 = 0; n2 < 16; n2++) v[n2] = lb[n2 * 16 + t];
    fft16(v);
#pragma unroll
    for (int k2 = 0; k2 < 16; k2++)
        g_work[base + (unsigned)(k2 * 16 + t)] = __float22bfloat162_rn(v[k2]);
}

// ---------------------------------------------------------------------------
template<unsigned ES, unsigned OS>
__global__ void __launch_bounds__(256, 3) k_passS() {
    __shared__ float2 sh[16 * SSTR];
    const int tid = threadIdx.x;
    const int bid = blockIdx.x;
    const unsigned vol   = (unsigned)bid >> 12;
    const unsigned r     = (unsigned)bid & 4095u;
    const unsigned outer = r >> 4;
    const unsigned w0    = (r & 15u) * 16u;
    const int wl = tid & 15;
    const int t  = tid >> 4;
    const unsigned base = vol * N3 + outer * OS + w0 + (unsigned)wl;

    float2 v[16];
#pragma unroll
    for (int n1 = 0; n1 < 16; n1++)
        v[n1] = __bfloat1622float2(g_work[base + (unsigned)(n1 * 16 + t) * ES]);
    fft16(v);
    twmul(v, t);
    float2* lb = &sh[wl * SSTR];
#pragma unroll
    for (int k1 = 0; k1 < 16; k1++) lb[t * 16 + k1] = v[k1];
    __syncthreads();
#pragma unroll
    for (int n2 = 0; n2 < 16; n2++) v[n2] = lb[n2 * 16 + t];
    fft16(v);
#pragma unroll
    for (int k2 = 0; k2 < 16; k2++)
        g_work[base + (unsigned)(k2 * 16 + t) * ES] = __float22bfloat162_rn(v[k2]);
}

// ---------------------------------------------------------------------------
// Fused D-pass + shell reduction + (last block) final loss.
// ---------------------------------------------------------------------------
extern __shared__ float2 dynsh[];

__device__ __forceinline__ int slbl(int c2) {
    return min((int)__fsqrt_rn((float)c2), 128);
}
__device__ __forceinline__ void flushBins(float* bins, int l,
                                          float s0, float s1, float s2) {
    atomicAdd(&bins[l * 3 + 0], s0);
    atomicAdd(&bins[l * 3 + 1], s1);
    atomicAdd(&bins[l * 3 + 2], s2);
}

// Self-mirror line binning: L holds Z of a line with w,h both self-mirror.
__device__ __forceinline__ void selfLine(const float2* L, int c2, float* bins, int t) {
    const int d0 = t * 8;
    int lcur = -1; float s0 = 0.f, s1 = 0.f, s2 = 0.f;
#pragma unroll
    for (int i = 0; i < 8; i++) {
        const int d = d0 + i;
        float q0, q1, q2;
        const float2 b = L[d];
        if (d == 0) {
            q0 = b.x * b.x + b.y * b.y;
            q1 = b.x * b.x - b.y * b.y;
            q2 = 2.0f * b.x * b.y;
        } else {
            const float2 a = L[256 - d];
            q0 = a.x * a.x + a.y * a.y + b.x * b.x + b.y * b.y;
            q1 = 2.0f * (a.x * b.x - a.y * b.y);
            q2 = 2.0f * (a.x * b.y + a.y * b.x);
        }
        const int l = slbl(c2 + d * d);
        if (l != lcur) {
            if (lcur >= 0) flushBins(bins, lcur, s0, s1, s2);
            lcur = l; s0 = q0; s1 = q1; s2 = q2;
        } else { s0 += q0; s1 += q1; s2 += q2; }
    }
    if (t == 15) {   // d = 128 self element
        const float2 b = L[128];
        const int l = slbl(c2 + 16384);
        float q0 = b.x * b.x + b.y * b.y;
        float q1 = b.x * b.x - b.y * b.y;
        float q2 = 2.0f * b.x * b.y;
        if (l != lcur) {
            if (lcur >= 0) flushBins(bins, lcur, s0, s1, s2);
            lcur = l; s0 = q0; s1 = q1; s2 = q2;
        } else { s0 += q0; s1 += q1; s2 += q2; }
    }
    if (lcur >= 0) flushBins(bins, lcur, s0, s1, s2);
}

__global__ void __launch_bounds__(256, 3) k_fusedD(float* __restrict__ out) {
    float2* bufA = dynsh;                       // 16*SSTR
    float2* bufB = dynsh + 16 * SSTR;           // 16*SSTR
    float*  sbf  = (float*)(dynsh + 32 * SSTR); // NCPY*BROW floats

    const int tid = threadIdx.x;

    const unsigned bid = blockIdx.x;
    const unsigned vol = bid >> 11;
    const unsigned r   = bid & 2047u;
    const unsigned volBase = vol * N3;

    unsigned hA, c;
    bool special = false;
    if (r < 2032u) { hA = 1u + (r >> 4); c = r & 15u; }
    else {
        unsigned idx = r - 2032u;
        hA = (idx < 8u) ? 0u : 128u;
        c  = idx & 7u;
        special = (c == 0u);
    }
    const unsigned hB = (256u - hA) & 255u;

    const int wl = tid & 15;
    const int t  = tid >> 4;

    const unsigned wA = 16u * c + (unsigned)wl;
    unsigned wB = (256u - 16u * c - (unsigned)wl) & 255u;
    if (special && wl == 0) wB = 128u;   // avoid duplicating w=0 line

    const unsigned baseA = volBase + hA * 256u + wA;
    const unsigned baseB = volBase + hB * 256u + wB;

    float2 v[16];
    float2* la = &bufA[wl * SSTR];
    float2* rb = &bufB[wl * SSTR];

    // ---- B lines: async bf16x2 staging into LOW half of own float2 slots ----
#pragma unroll
    for (int n1 = 0; n1 < 16; n1++)
        cpa4(&rb[t * 16 + n1], &g_work[baseB + (unsigned)(n1 * 16 + t) * 65536u]);
    cpa_commit();

    // ---- A lines into registers (bf16 -> fp32) ----
#pragma unroll
    for (int n1 = 0; n1 < 16; n1++)
        v[n1] = __bfloat1622float2(g_work[baseA + (unsigned)(n1 * 16 + t) * 65536u]);

    for (int i = tid; i < NCPY * BROW; i += 256) sbf[i] = 0.0f;

    // ---- phase A ----
    fft16(v);
    twmul(v, t);
#pragma unroll
    for (int k1 = 0; k1 < 16; k1++) la[t * 16 + k1] = v[k1];
    __syncthreads();                                    // (1)
#pragma unroll
    for (int n2 = 0; n2 < 16; n2++) v[n2] = la[n2 * 16 + t];
    fft16(v);
#pragma unroll
    for (int k2 = 0; k2 < 16; k2++) la[k2 * 16 + t] = v[k2];  // own slots

    // ---- phase B from staged bf16 (own slots; per-thread wait only) ----
    cpa_wait0();
#pragma unroll
    for (int n1 = 0; n1 < 16; n1++) {
        __nv_bfloat162 raw = *reinterpret_cast<const __nv_bfloat162*>(&rb[t * 16 + n1]);
        v[n1] = __bfloat1622float2(raw);
    }
    fft16(v);
    twmul(v, t);
#pragma unroll
    for (int k1 = 0; k1 < 16; k1++) rb[t * 16 + k1] = v[k1];  // overwrite own slots
    __syncthreads();                                    // (2)
#pragma unroll
    for (int n2 = 0; n2 < 16; n2++) v[n2] = rb[n2 * 16 + t];
    fft16(v);
#pragma unroll
    for (int k2 = 0; k2 < 16; k2++) rb[k2 * 16 + t] = v[k2];  // own slots
    __syncthreads();                                    // (3)

    // ---- binning: half-line windows, 4 elements per label sample ----
    float* bins = sbf + (wl & 3) * BROW;

    if (special && wl == 0) {
        const int shh = (hB < 128u) ? (int)hB : (int)hB - 256;
        selfLine(&bufA[0], shh * shh,          bins, t);   // (h, w=0)
        selfLine(&bufB[0], shh * shh + 16384,  bins, t);   // (h, w=128)
    } else {
        const int shh = (hB < 128u) ? (int)hB : (int)hB - 256;
        const int sww = (wB < 128u) ? (int)wB : (int)wB - 256;
        const int c2hw = shh * shh + sww * sww;
        const float2* A = la;
        const float2* B = rb;
        const int d0 = t * 8;
        int lcur = -1; float s0 = 0.f, s1 = 0.f, s2 = 0.f;
#pragma unroll
        for (int i = 0; i < 8; i++) {
            const int d = d0 + i;
            float q0, q1, q2;
            if (d == 0) {
                const float2 a = A[0], b = B[0];
                q0 = a.x * a.x + a.y * a.y + b.x * b.x + b.y * b.y;
                q1 = 2.0f * (a.x * b.x - a.y * b.y);
                q2 = 2.0f * (a.x * b.y + a.y * b.x);
            } else {
                const float2 b1 = B[d],       a1 = A[256 - d];
                const float2 b2 = B[256 - d], a2 = A[d];
                q0 = a1.x * a1.x + a1.y * a1.y + b1.x * b1.x + b1.y * b1.y
                   + a2.x * a2.x + a2.y * a2.y + b2.x * b2.x + b2.y * b2.y;
                q1 = 2.0f * (a1.x * b1.x - a1.y * b1.y + a2.x * b2.x - a2.y * b2.y);
                q2 = 2.0f * (a1.x * b1.y + a1.y * b1.x + a2.x * b2.y + a2.y * b2.x);
            }
            const int l = slbl(c2hw + d * d);
            if (l != lcur) {
                if (lcur >= 0) flushBins(bins, lcur, s0, s1, s2);
                lcur = l; s0 = q0; s1 = q1; s2 = q2;
            } else { s0 += q0; s1 += q1; s2 += q2; }
        }
        if (t == 15) {   // d = 128: single pair (A[128], B[128])
            const float2 a = A[128], b = B[128];
            const float q0 = a.x * a.x + a.y * a.y + b.x * b.x + b.y * b.y;
            const float q1 = 2.0f * (a.x * b.x - a.y * b.y);
            const float q2 = 2.0f * (a.x * b.y + a.y * b.x);
            const int l = slbl(c2hw + 16384);
            if (l != lcur) {
                if (lcur >= 0) flushBins(bins, lcur, s0, s1, s2);
                lcur = l; s0 = q0; s1 = q1; s2 = q2;
            } else { s0 += q0; s1 += q1; s2 += q2; }
        }
        if (lcur >= 0) flushBins(bins, lcur, s0, s1, s2);
    }
    __syncthreads();

    for (int i = tid; i < 387; i += 256) {
        float s = 0.0f;
#pragma unroll
        for (int cpy = 0; cpy < NCPY; cpy++) s += sbf[cpy * BROW + i];
        atomicAdd(&g_bins[vol * 400u + (unsigned)i], (double)s);
    }

    // ---- last block computes the final loss (merged k_final) ----
    __threadfence();
    __shared__ int isLast;
    if (tid == 0) {
        int cdone = atomicAdd(&g_ctr, 1);
        isLast = (cdone == (int)gridDim.x - 1);
    }
    __syncthreads();
    if (isLast) {
        __shared__ double red[256];
        const unsigned fvol = (unsigned)tid >> 7;
        const unsigned bin  = (unsigned)tid & 127u;
        const double S0 = g_bins[fvol * 400u + bin * 3u + 0u];
        const double S1 = g_bins[fvol * 400u + bin * 3u + 1u];
        const double S2 = g_bins[fvol * 400u + bin * 3u + 2u];
        const double num = 0.5 * S2;
        const double d1 = 0.5 * (S0 + S1);
        const double d2 = 0.5 * (S0 - S1);
        red[tid] = (num * num) / (d1 * d2 + 1e-8);
        __syncthreads();
        for (int s = 128; s > 0; s >>= 1) {
            if (tid < s) red[tid] += red[tid + s];
            __syncthreads();
        }
        if (tid == 0) {
            out[0] = (float)(1.0 - red[0] / 256.0);
            g_ctr = 0;                       // reset for next graph replay
        }
    }
}

// ---------------------------------------------------------------------------
extern "C" void kernel_launch(void* const* d_in, const int* in_sizes, int n_in,
                              void* d_out, int out_size) {
    const float* ref  = (const float*)d_in[0];
    const float* pred = (const float*)d_in[1];
    float* out = (float*)d_out;

    const int FUSED_SMEM = 32 * SSTR * 8 + NCPY * BROW * 4;  // 72064 B
    cudaFuncSetAttribute(k_fusedD, cudaFuncAttributeMaxDynamicSharedMemorySize,
                         FUSED_SMEM);

    k_pass0<<<8192, 256>>>(ref, pred);                 // zero bins + pack + FFT along W
    k_passS<256u, 65536u><<<8192, 256>>>();            // FFT along H
    k_fusedD<<<4096, 256, FUSED_SMEM>>>(out);          // FFT along D + binning + loss
}

// round 14
// speedup vs baseline: 1.4043x; 1.0005x over previous
#include <cuda_runtime.h>
#include <cuda_bf16.h>
#include <math.h>

#define N3   16777216u           // 256^3
#define SSTR 257                 // smem row stride (float2)
#define BROW 392                 // per-copy bin stride (floats), 3*129=387 used
#define NCPY 4

__device__ __nv_bfloat162 g_work[2u * N3];  // packed ref+i*pred spectrum (bf16), 134MB
__device__ double g_bins[800];              // [vol][label*3+comp]
__device__ int    g_ctr = 0;                // last-block counter (self-resetting)

// ---------------------------------------------------------------------------
// constexpr twiddles: folded to FFMA immediates by nvcc (no LDC on sm_103a).
// ---------------------------------------------------------------------------
__device__ constexpr float TWC[8] = { 1.0f,  0.9238795325112867f,  0.7071067811865476f,
                                      0.3826834323650898f, 0.0f, -0.3826834323650898f,
                                     -0.7071067811865476f, -0.9238795325112867f };
__device__ constexpr float TWS[8] = { 0.0f, -0.3826834323650898f, -0.7071067811865476f,
                                     -0.9238795325112867f, -1.0f, -0.9238795325112867f,
                                     -0.7071067811865476f, -0.3826834323650898f };

__device__ __forceinline__ void cswap(float2& a, float2& b) { float2 t = a; a = b; b = t; }

__device__ __forceinline__ void fft16(float2 v[16]) {
    cswap(v[1], v[8]);  cswap(v[2], v[4]);  cswap(v[3], v[12]);
    cswap(v[5], v[10]); cswap(v[7], v[14]); cswap(v[11], v[13]);
#pragma unroll
    for (int s = 1; s <= 4; s++) {
        const int m = 1 << s, hm = m >> 1;
#pragma unroll
        for (int k = 0; k < 16; k += m) {
#pragma unroll
            for (int j = 0; j < hm; j++) {
                const float wr = TWC[j << (4 - s)];   // literal -> folded
                const float wi = TWS[j << (4 - s)];   // literal -> folded
                float2 a = v[k + j], b = v[k + j + hm];
                float tr = b.x * wr - b.y * wi;
                float ti = b.x * wi + b.y * wr;
                v[k + j]      = make_float2(a.x + tr, a.y + ti);
                v[k + j + hm] = make_float2(a.x - tr, a.y - ti);
            }
        }
    }
}

__device__ __forceinline__ void twmul(float2 v[16], int t) {
    float bs, bc;
    sincospif(-(float)t / 128.0f, &bs, &bc);
    float wr = bc, wi = bs;
#pragma unroll
    for (int k1 = 1; k1 < 16; k1++) {
        float xr = v[k1].x * wr - v[k1].y * wi;
        float xi = v[k1].x * wi + v[k1].y * wr;
        v[k1] = make_float2(xr, xi);
        float nr = wr * bc - wi * bs;
        float ni = wr * bs + wi * bc;
        wr = nr; wi = ni;
    }
}

// cp.async helpers (LDGSTS, 4-byte)
__device__ __forceinline__ void cpa4(void* smem_dst, const void* gmem_src) {
    unsigned saddr = (unsigned)__cvta_generic_to_shared(smem_dst);
    asm volatile("cp.async.ca.shared.global [%0], [%1], 4;\n"
                 :: "r"(saddr), "l"(gmem_src));
}
__device__ __forceinline__ void cpa_commit() {
    asm volatile("cp.async.commit_group;\n" ::: "memory");
}
__device__ __forceinline__ void cpa_wait0() {
    asm volatile("cp.async.wait_group 0;\n" ::: "memory");
}

// ---------------------------------------------------------------------------
__global__ void __launch_bounds__(256, 4)
k_pass0(const float* __restrict__ ref, const float* __restrict__ pred) {
    __shared__ float2 sh[16 * SSTR];
    const int tid = threadIdx.x;
    const int bid = blockIdx.x;

    // block 0 clears the bin accumulators (pass0 precedes fusedD).
    if (bid == 0) {
        for (int i = tid; i < 800; i += 256) g_bins[i] = 0.0;
    }

    const unsigned vol  = (unsigned)bid >> 12;
    const unsigned tile = (unsigned)bid & 4095u;
    const int l = tid >> 4;
    const int t = tid & 15;
    const unsigned base = vol * N3 + (tile * 16u + (unsigned)l) * 256u;

    float2 v[16];
#pragma unroll
    for (int n1 = 0; n1 < 16; n1++) {
        unsigned e = base + (unsigned)(n1 * 16 + t);
        v[n1] = make_float2(ref[e], pred[e]);
    }
    fft16(v);
    twmul(v, t);
    float2* lb = &sh[l * SSTR];
#pragma unroll
    for (int k1 = 0; k1 < 16; k1++) lb[t * 16 + k1] = v[k1];
    __syncthreads();
#pragma unroll
    for (int n2 = 0; n2 < 16; n2++) v[n2] = lb[n2 * 16 + t];
    fft16(v);
#pragma unroll
    for (int k2 = 0; k2 < 16; k2++)
        g_work[base + (unsigned)(k2 * 16 + t)] = __float22bfloat162_rn(v[k2]);
}

// ---------------------------------------------------------------------------
template<unsigned ES, unsigned OS>
__global__ void __launch_bounds__(256, 4) k_passS() {
    __shared__ float2 sh[16 * SSTR];
    const int tid = threadIdx.x;
    const int bid = blockIdx.x;
    const unsigned vol   = (unsigned)bid >> 12;
    const unsigned r     = (unsigned)bid & 4095u;
    const unsigned outer = r >> 4;
    const unsigned w0    = (r & 15u) * 16u;
    const int wl = tid & 15;
    const int t  = tid >> 4;
    const unsigned base = vol * N3 + outer * OS + w0 + (unsigned)wl;

    float2 v[16];
#pragma unroll
    for (int n1 = 0; n1 < 16; n1++)
        v[n1] = __bfloat1622float2(g_work[base + (unsigned)(n1 * 16 + t) * ES]);
    fft16(v);
    twmul(v, t);
    float2* lb = &sh[wl * SSTR];
#pragma unroll
    for (int k1 = 0; k1 < 16; k1++) lb[t * 16 + k1] = v[k1];
    __syncthreads();
#pragma unroll
    for (int n2 = 0; n2 < 16; n2++) v[n2] = lb[n2 * 16 + t];
    fft16(v);
#pragma unroll
    for (int k2 = 0; k2 < 16; k2++)
        g_work[base + (unsigned)(k2 * 16 + t) * ES] = __float22bfloat162_rn(v[k2]);
}

// ---------------------------------------------------------------------------
// Fused D-pass + shell reduction + (last block) final loss.
// ---------------------------------------------------------------------------
extern __shared__ float2 dynsh[];

__device__ __forceinline__ int slbl(int c2) {
    return min((int)__fsqrt_rn((float)c2), 128);
}
__device__ __forceinline__ void flushBins(float* bins, int l,
                                          float s0, float s1, float s2) {
    atomicAdd(&bins[l * 3 + 0], s0);
    atomicAdd(&bins[l * 3 + 1], s1);
    atomicAdd(&bins[l * 3 + 2], s2);
}

// Self-mirror line binning: L holds Z of a line with w,h both self-mirror.
__device__ __forceinline__ void selfLine(const float2* L, int c2, float* bins, int t) {
    const int d0 = t * 8;
    int lcur = -1; float s0 = 0.f, s1 = 0.f, s2 = 0.f;
#pragma unroll
    for (int i = 0; i < 8; i++) {
        const int d = d0 + i;
        float q0, q1, q2;
        const float2 b = L[d];
        if (d == 0) {
            q0 = b.x * b.x + b.y * b.y;
            q1 = b.x * b.x - b.y * b.y;
            q2 = 2.0f * b.x * b.y;
        } else {
            const float2 a = L[256 - d];
            q0 = a.x * a.x + a.y * a.y + b.x * b.x + b.y * b.y;
            q1 = 2.0f * (a.x * b.x - a.y * b.y);
            q2 = 2.0f * (a.x * b.y + a.y * b.x);
        }
        const int l = slbl(c2 + d * d);
        if (l != lcur) {
            if (lcur >= 0) flushBins(bins, lcur, s0, s1, s2);
            lcur = l; s0 = q0; s1 = q1; s2 = q2;
        } else { s0 += q0; s1 += q1; s2 += q2; }
    }
    if (t == 15) {   // d = 128 self element
        const float2 b = L[128];
        const int l = slbl(c2 + 16384);
        float q0 = b.x * b.x + b.y * b.y;
        float q1 = b.x * b.x - b.y * b.y;
        float q2 = 2.0f * b.x * b.y;
        if (l != lcur) {
            if (lcur >= 0) flushBins(bins, lcur, s0, s1, s2);
            lcur = l; s0 = q0; s1 = q1; s2 = q2;
        } else { s0 += q0; s1 += q1; s2 += q2; }
    }
    if (lcur >= 0) flushBins(bins, lcur, s0, s1, s2);
}

__global__ void __launch_bounds__(256, 3) k_fusedD(float* __restrict__ out) {
    float2* bufA = dynsh;                       // 16*SSTR
    float2* bufB = dynsh + 16 * SSTR;           // 16*SSTR
    float*  sbf  = (float*)(dynsh + 32 * SSTR); // NCPY*BROW floats

    const int tid = threadIdx.x;

    const unsigned bid = blockIdx.x;
    const unsigned vol = bid >> 11;
    const unsigned r   = bid & 2047u;
    const unsigned volBase = vol * N3;

    unsigned hA, c;
    bool special = false;
    if (r < 2032u) { hA = 1u + (r >> 4); c = r & 15u; }
    else {
        unsigned idx = r - 2032u;
        hA = (idx < 8u) ? 0u : 128u;
        c  = idx & 7u;
        special = (c == 0u);
    }
    const unsigned hB = (256u - hA) & 255u;

    const int wl = tid & 15;
    const int t  = tid >> 4;

    const unsigned wA = 16u * c + (unsigned)wl;
    unsigned wB = (256u - 16u * c - (unsigned)wl) & 255u;
    if (special && wl == 0) wB = 128u;   // avoid duplicating w=0 line

    const unsigned baseA = volBase + hA * 256u + wA;
    const unsigned baseB = volBase + hB * 256u + wB;

    float2 v[16];
    float2* la = &bufA[wl * SSTR];
    float2* rb = &bufB[wl * SSTR];

    // ---- B lines: async bf16x2 staging into LOW half of own float2 slots ----
#pragma unroll
    for (int n1 = 0; n1 < 16; n1++)
        cpa4(&rb[t * 16 + n1], &g_work[baseB + (unsigned)(n1 * 16 + t) * 65536u]);
    cpa_commit();

    // ---- A lines into registers (bf16 -> fp32) ----
#pragma unroll
    for (int n1 = 0; n1 < 16; n1++)
        v[n1] = __bfloat1622float2(g_work[baseA + (unsigned)(n1 * 16 + t) * 65536u]);

    for (int i = tid; i < NCPY * BROW; i += 256) sbf[i] = 0.0f;

    // ---- phase A ----
    fft16(v);
    twmul(v, t);
#pragma unroll
    for (int k1 = 0; k1 < 16; k1++) la[t * 16 + k1] = v[k1];
    __syncthreads();                                    // (1)
#pragma unroll
    for (int n2 = 0; n2 < 16; n2++) v[n2] = la[n2 * 16 + t];
    fft16(v);
#pragma unroll
    for (int k2 = 0; k2 < 16; k2++) la[k2 * 16 + t] = v[k2];  // own slots

    // ---- phase B from staged bf16 (own slots; per-thread wait only) ----
    cpa_wait0();
#pragma unroll
    for (int n1 = 0; n1 < 16; n1++) {
        __nv_bfloat162 raw = *reinterpret_cast<const __nv_bfloat162*>(&rb[t * 16 + n1]);
        v[n1] = __bfloat1622float2(raw);
    }
    fft16(v);
    twmul(v, t);
#pragma unroll
    for (int k1 = 0; k1 < 16; k1++) rb[t * 16 + k1] = v[k1];  // overwrite own slots
    __syncthreads();                                    // (2)
#pragma unroll
    for (int n2 = 0; n2 < 16; n2++) v[n2] = rb[n2 * 16 + t];
    fft16(v);
#pragma unroll
    for (int k2 = 0; k2 < 16; k2++) rb[k2 * 16 + t] = v[k2];  // own slots
    __syncthreads();                                    // (3)

    // ---- binning: half-line windows, 4 elements per label sample ----
    float* bins = sbf + (wl & 3) * BROW;

    if (special && wl == 0) {
        const int shh = (hB < 128u) ? (int)hB : (int)hB - 256;
        selfLine(&bufA[0], shh * shh,          bins, t);   // (h, w=0)
        selfLine(&bufB[0], shh * shh + 16384,  bins, t);   // (h, w=128)
    } else {
        const int shh = (hB < 128u) ? (int)hB : (int)hB - 256;
        const int sww = (wB < 128u) ? (int)wB : (int)wB - 256;
        const int c2hw = shh * shh + sww * sww;
        const float2* A = la;
        const float2* B = rb;
        const int d0 = t * 8;
        int lcur = -1; float s0 = 0.f, s1 = 0.f, s2 = 0.f;
#pragma unroll
        for (int i = 0; i < 8; i++) {
            const int d = d0 + i;
            float q0, q1, q2;
            if (d == 0) {
                const float2 a = A[0], b = B[0];
                q0 = a.x * a.x + a.y * a.y + b.x * b.x + b.y * b.y;
                q1 = 2.0f * (a.x * b.x - a.y * b.y);
                q2 = 2.0f * (a.x * b.y + a.y * b.x);
            } else {
                const float2 b1 = B[d],       a1 = A[256 - d];
                const float2 b2 = B[256 - d], a2 = A[d];
                q0 = a1.x * a1.x + a1.y * a1.y + b1.x * b1.x + b1.y * b1.y
                   + a2.x * a2.x + a2.y * a2.y + b2.x * b2.x + b2.y * b2.y;
                q1 = 2.0f * (a1.x * b1.x - a1.y * b1.y + a2.x * b2.x - a2.y * b2.y);
                q2 = 2.0f * (a1.x * b1.y + a1.y * b1.x + a2.x * b2.y + a2.y * b2.x);
            }
            const int l = slbl(c2hw + d * d);
            if (l != lcur) {
                if (lcur >= 0) flushBins(bins, lcur, s0, s1, s2);
                lcur = l; s0 = q0; s1 = q1; s2 = q2;
            } else { s0 += q0; s1 += q1; s2 += q2; }
        }
        if (t == 15) {   // d = 128: single pair (A[128], B[128])
            const float2 a = A[128], b = B[128];
            const float q0 = a.x * a.x + a.y * a.y + b.x * b.x + b.y * b.y;
            const float q1 = 2.0f * (a.x * b.x - a.y * b.y);
            const float q2 = 2.0f * (a.x * b.y + a.y * b.x);
            const int l = slbl(c2hw + 16384);
            if (l != lcur) {
                if (lcur >= 0) flushBins(bins, lcur, s0, s1, s2);
                lcur = l; s0 = q0; s1 = q1; s2 = q2;
            } else { s0 += q0; s1 += q1; s2 += q2; }
        }
        if (lcur >= 0) flushBins(bins, lcur, s0, s1, s2);
    }
    __syncthreads();

    for (int i = tid; i < 387; i += 256) {
        float s = 0.0f;
#pragma unroll
        for (int cpy = 0; cpy < NCPY; cpy++) s += sbf[cpy * BROW + i];
        atomicAdd(&g_bins[vol * 400u + (unsigned)i], (double)s);
    }

    // ---- last block computes the final loss (merged k_final) ----
    __threadfence();
    __shared__ int isLast;
    if (tid == 0) {
        int cdone = atomicAdd(&g_ctr, 1);
        isLast = (cdone == (int)gridDim.x - 1);
    }
    __syncthreads();
    if (isLast) {
        __shared__ double red[256];
        const unsigned fvol = (unsigned)tid >> 7;
        const unsigned bin  = (unsigned)tid & 127u;
        const double S0 = g_bins[fvol * 400u + bin * 3u + 0u];
        const double S1 = g_bins[fvol * 400u + bin * 3u + 1u];
        const double S2 = g_bins[fvol * 400u + bin * 3u + 2u];
        const double num = 0.5 * S2;
        const double d1 = 0.5 * (S0 + S1);
        const double d2 = 0.5 * (S0 - S1);
        red[tid] = (num * num) / (d1 * d2 + 1e-8);
        __syncthreads();
        for (int s = 128; s > 0; s >>= 1) {
            if (tid < s) red[tid] += red[tid + s];
            __syncthreads();
        }
        if (tid == 0) {
            out[0] = (float)(1.0 - red[0] / 256.0);
            g_ctr = 0;                       // reset for next graph replay
        }
    }
}

// ---------------------------------------------------------------------------
extern "C" void kernel_launch(void* const* d_in, const int* in_sizes, int n_in,
                              void* d_out, int out_size) {
    const float* ref  = (const float*)d_in[0];
    const float* pred = (const float*)d_in[1];
    float* out = (float*)d_out;

    const int FUSED_SMEM = 32 * SSTR * 8 + NCPY * BROW * 4;  // 72064 B
    cudaFuncSetAttribute(k_fusedD, cudaFuncAttributeMaxDynamicSharedMemorySize,
                         FUSED_SMEM);

    k_pass0<<<8192, 256>>>(ref, pred);                 // zero bins + pack + FFT along W
    k_passS<256u, 65536u><<<8192, 256>>>();            // FFT along H
    k_fusedD<<<4096, 256, FUSED_SMEM>>>(out);          // FFT along D + binning + loss
}